// round 3
// baseline (speedup 1.0000x reference)
#include <cuda_runtime.h>
#include <math.h>

#define Td 128
#define Bd 256
#define Xd 32
#define Ud 8
#define ADd 24
#define Hd 256
#define NT 256
#define GE 2
#define MINV 0.01f
#define MAXV 1.0f
#define EPSV 1e-6f

// smem row strides (avoid bank conflicts on strided column access)
#define SX 33   // 32x32 matrices
#define SC 33   // 24x32 matrices
#define SS 49   // 24x48 augmented
#define SG 25   // 32x24 gain

struct Smem {
    float qmean[GE][32];
    float pmean[GE][32];
    float qcov[GE][32 * SX];
    float pcov[GE][32 * SX];
    float h1[GE][Hd];
    float h2[GE][Hd];
    float Amat[GE][32 * SX];
    float T1[GE][32 * SX];
    float NC[GE][32 * SX];
    float Bmt[GE][Xd * Ud];
    float Cm[GE][ADd * SC];
    float Ccov[GE][ADd * SC];
    float Saug[GE][ADd * SS];
    float Gm[GE][32 * SG];
    float nx[GE][32];
    float na[GE][32];
    float innov[GE][32];
    float ut[GE][8];
    float at[GE][24];
    float piv[4];
    float fcol[GE][24];
};

__device__ __forceinline__ float sigv(float z) {
    return MINV + (MAXV - MINV) / (1.0f + expf(-z));
}

// Dual-element GEMV: out[e][p] = bias[p] + dot(W[p,:], x_e). One global weight
// load serves both elements (the whole point of GE=2: halves L2 traffic).
template <int K, class F>
__device__ __forceinline__ void gemv2(const float* __restrict__ W,
                                      const float* __restrict__ bias,
                                      const float* __restrict__ x0,
                                      const float* __restrict__ x1,
                                      int P, F store) {
    const float4* a0 = reinterpret_cast<const float4*>(x0);
    const float4* a1 = reinterpret_cast<const float4*>(x1);
    for (int p = (int)threadIdx.x; p < P; p += NT) {
        const float4* w = reinterpret_cast<const float4*>(W + (size_t)p * K);
        float s0a = 0.f, s0b = 0.f, s1a = 0.f, s1b = 0.f;
#pragma unroll 8
        for (int k = 0; k < K / 4; k++) {
            float4 wv = w[k];
            float4 v0 = a0[k];
            float4 v1 = a1[k];
            s0a = fmaf(wv.x, v0.x, s0a); s0b = fmaf(wv.y, v0.y, s0b);
            s0a = fmaf(wv.z, v0.z, s0a); s0b = fmaf(wv.w, v0.w, s0b);
            s1a = fmaf(wv.x, v1.x, s1a); s1b = fmaf(wv.y, v1.y, s1b);
            s1a = fmaf(wv.z, v1.z, s1a); s1b = fmaf(wv.w, v1.w, s1b);
        }
        float bb = bias[p];
        store(p, s0a + s0b + bb, s1a + s1b + bb);
    }
}

__global__ void __launch_bounds__(NT, 1)
kf_kernel(const float* __restrict__ u, const float* __restrict__ a,
          const float* __restrict__ W1, const float* __restrict__ b1,
          const float* __restrict__ W2, const float* __restrict__ b2,
          const float* __restrict__ WA, const float* __restrict__ bA,
          const float* __restrict__ WB, const float* __restrict__ bB,
          const float* __restrict__ WC, const float* __restrict__ bC,
          const float* __restrict__ Wnx, const float* __restrict__ bnx,
          const float* __restrict__ Wna, const float* __restrict__ bna,
          const float* __restrict__ alpha_p, float* __restrict__ out) {
    extern __shared__ char smem_raw[];
    Smem& s = *reinterpret_cast<Smem*>(smem_raw);
    const int tid = (int)threadIdx.x;
    const int b0 = (int)blockIdx.x * GE;
    const float alpha = alpha_p[0];

    const size_t PM_OFF = 0;
    const size_t PC_OFF = (size_t)Td * Bd * Xd;                   // 1048576
    const size_t QM_OFF = PC_OFF + (size_t)Td * Bd * Xd * Xd;     // 34603008
    const size_t QC_OFF = QM_OFF + (size_t)Td * Bd * Xd;          // 35651584

    for (int t = 0; t < Td; t++) {
        if (t > 0) {
            // ================= PRIOR: dyn(qmean) -> A, B, nx =================
            for (int i = tid; i < GE * Ud; i += NT) {
                int e = i >> 3, j = i & 7;
                s.ut[e][j] = u[((size_t)(t - 1) * Bd + b0 + e) * Ud + j];
            }
            gemv2<32>(W1, b1, s.qmean[0], s.qmean[1], Hd,
                      [&](int p, float v0, float v1) {
                          s.h1[0][p] = fmaxf(v0, 0.f);
                          s.h1[1][p] = fmaxf(v1, 0.f);
                      });
            __syncthreads();
            gemv2<256>(W2, b2, s.h1[0], s.h1[1], Hd,
                       [&](int p, float v0, float v1) {
                           s.h2[0][p] = fmaxf(v0, 0.f);
                           s.h2[1][p] = fmaxf(v1, 0.f);
                       });
            __syncthreads();
            gemv2<256>(WA, bA, s.h2[0], s.h2[1], Xd * Xd,
                       [&](int p, float v0, float v1) {
                           int i = p >> 5, j = p & 31;
                           float d = (i == j) ? 1.f : 0.f;
                           s.Amat[0][i * SX + j] = d + alpha * v0;
                           s.Amat[1][i * SX + j] = d + alpha * v1;
                       });
            gemv2<256>(WB, bB, s.h2[0], s.h2[1], Xd * Ud,
                       [&](int p, float v0, float v1) {
                           s.Bmt[0][p] = v0;
                           s.Bmt[1][p] = v1;
                       });
            gemv2<256>(Wnx, bnx, s.h2[0], s.h2[1], Xd,
                       [&](int p, float v0, float v1) {
                           s.nx[0][p] = sigv(v0);
                           s.nx[1][p] = sigv(v1);
                       });
            __syncthreads();
            // pmean = A@qmean + B@u  ;  T1 = A@qcov
            for (int idx = tid; idx < GE * 32; idx += NT) {
                int e = idx >> 5, i = idx & 31;
                float sm = 0.f;
                for (int j = 0; j < 32; j++)
                    sm = fmaf(s.Amat[e][i * SX + j], s.qmean[e][j], sm);
                for (int j = 0; j < 8; j++)
                    sm = fmaf(s.Bmt[e][i * 8 + j], s.ut[e][j], sm);
                s.pmean[e][i] = sm;
            }
            for (int idx = tid; idx < GE * 1024; idx += NT) {
                int e = idx >> 10, r = idx & 1023, i = r >> 5, k = r & 31;
                float sm = 0.f;
#pragma unroll
                for (int j = 0; j < 32; j++)
                    sm = fmaf(s.Amat[e][i * SX + j], s.qcov[e][j * SX + k], sm);
                s.T1[e][i * SX + k] = sm;
            }
            __syncthreads();
            // NC = T1 @ A^T + diag(nx)
            for (int idx = tid; idx < GE * 1024; idx += NT) {
                int e = idx >> 10, r = idx & 1023, i = r >> 5, j = r & 31;
                float sm = (i == j) ? s.nx[e][i] : 0.f;
#pragma unroll
                for (int k = 0; k < 32; k++)
                    sm = fmaf(s.T1[e][i * SX + k], s.Amat[e][j * SX + k], sm);
                s.NC[e][i * SX + j] = sm;
            }
            __syncthreads();
            // pcov = 0.5(NC+NC^T) + eps I ; write prior outputs
            for (int idx = tid; idx < GE * 1024; idx += NT) {
                int e = idx >> 10, r = idx & 1023, i = r >> 5, j = r & 31;
                float v = 0.5f * (s.NC[e][i * SX + j] + s.NC[e][j * SX + i]) +
                          ((i == j) ? EPSV : 0.f);
                s.pcov[e][i * SX + j] = v;
                out[PC_OFF + ((size_t)t * Bd + b0 + e) * 1024 + r] = v;
            }
            for (int idx = tid; idx < GE * 32; idx += NT) {
                int e = idx >> 5, i = idx & 31;
                out[PM_OFF + ((size_t)t * Bd + b0 + e) * 32 + i] = s.pmean[e][i];
            }
            __syncthreads();
        } else {
            // t == 0: pm0 = 0, pc0 = I
            for (int idx = tid; idx < GE * 32; idx += NT) {
                int e = idx >> 5, i = idx & 31;
                s.pmean[e][i] = 0.f;
                out[PM_OFF + ((size_t)(b0 + e)) * 32 + i] = 0.f;
            }
            for (int idx = tid; idx < GE * 1024; idx += NT) {
                int e = idx >> 10, r = idx & 1023, i = r >> 5, j = r & 31;
                float v = (i == j) ? 1.f : 0.f;
                s.pcov[e][i * SX + j] = v;
                out[PC_OFF + ((size_t)(b0 + e)) * 1024 + r] = v;
            }
            __syncthreads();
        }

        // ================= POST: dyn(pmean) -> C, na =================
        for (int i = tid; i < GE * ADd; i += NT) {
            int e = i / ADd, j = i % ADd;
            s.at[e][j] = a[((size_t)t * Bd + b0 + e) * ADd + j];
        }
        gemv2<32>(W1, b1, s.pmean[0], s.pmean[1], Hd,
                  [&](int p, float v0, float v1) {
                      s.h1[0][p] = fmaxf(v0, 0.f);
                      s.h1[1][p] = fmaxf(v1, 0.f);
                  });
        __syncthreads();
        gemv2<256>(W2, b2, s.h1[0], s.h1[1], Hd,
                   [&](int p, float v0, float v1) {
                       s.h2[0][p] = fmaxf(v0, 0.f);
                       s.h2[1][p] = fmaxf(v1, 0.f);
                   });
        __syncthreads();
        gemv2<256>(WC, bC, s.h2[0], s.h2[1], ADd * Xd,
                   [&](int p, float v0, float v1) {
                       int i = p >> 5, j = p & 31;
                       s.Cm[0][i * SC + j] = v0;
                       s.Cm[1][i * SC + j] = v1;
                   });
        gemv2<256>(Wna, bna, s.h2[0], s.h2[1], ADd,
                   [&](int p, float v0, float v1) {
                       s.na[0][p] = sigv(v0);
                       s.na[1][p] = sigv(v1);
                   });
        __syncthreads();
        // Ccov = C @ pcov   [24x32]
        for (int idx = tid; idx < GE * ADd * 32; idx += NT) {
            int e = idx / (ADd * 32), r = idx % (ADd * 32), i = r >> 5, k = r & 31;
            float sm = 0.f;
#pragma unroll
            for (int j = 0; j < 32; j++)
                sm = fmaf(s.Cm[e][i * SC + j], s.pcov[e][j * SX + k], sm);
            s.Ccov[e][i * SC + k] = sm;
        }
        __syncthreads();
        // Saug = [ S | I ],  S = Ccov @ C^T + diag(na)
        for (int idx = tid; idx < GE * ADd * ADd; idx += NT) {
            int e = idx / (ADd * ADd), r = idx % (ADd * ADd), i = r / ADd, l = r % ADd;
            float sm = (i == l) ? s.na[e][i] : 0.f;
#pragma unroll
            for (int k = 0; k < 32; k++)
                sm = fmaf(s.Ccov[e][i * SC + k], s.Cm[e][l * SC + k], sm);
            s.Saug[e][i * SS + l] = sm;
            s.Saug[e][i * SS + ADd + l] = (i == l) ? 1.f : 0.f;
        }
        __syncthreads();
        // Gauss-Jordan inverse of SPD S (pinv == inv here: S >= 0.01*I)
        for (int j = 0; j < ADd; j++) {
            if (tid < GE) s.piv[tid] = 1.0f / s.Saug[tid][j * SS + j];
            if (tid >= 32 && tid < 32 + GE * ADd) {
                int q = tid - 32, e = q / ADd, i = q % ADd;
                s.fcol[e][i] = s.Saug[e][i * SS + j];
            }
            __syncthreads();
            if (tid < GE * 48) {
                int e = tid / 48, k = tid % 48;
                s.Saug[e][j * SS + k] *= s.piv[e];
            }
            __syncthreads();
            for (int idx = tid; idx < GE * ADd * 48; idx += NT) {
                int e = idx / (ADd * 48), r = idx % (ADd * 48), i = r / 48, k = r % 48;
                if (i != j)
                    s.Saug[e][i * SS + k] -= s.fcol[e][i] * s.Saug[e][j * SS + k];
            }
            __syncthreads();
        }
        // G = Ccov^T @ Sinv  (cov symmetric => cov@C^T = Ccov^T) ; innov
        for (int idx = tid; idx < GE * 32 * ADd; idx += NT) {
            int e = idx / (32 * ADd), r = idx % (32 * ADd), i = r / ADd, l = r % ADd;
            float sm = 0.f;
#pragma unroll
            for (int k = 0; k < ADd; k++)
                sm = fmaf(s.Ccov[e][k * SC + i], s.Saug[e][k * SS + ADd + l], sm);
            s.Gm[e][i * SG + l] = sm;
        }
        for (int idx = tid + GE * 32 * ADd; idx < GE * 32 * ADd + GE * ADd; idx += NT) {
            int q = idx - GE * 32 * ADd;
            int e = q / ADd, i = q % ADd;
            float sm = 0.f;
            for (int j = 0; j < 32; j++)
                sm = fmaf(s.Cm[e][i * SC + j], s.pmean[e][j], sm);
            s.innov[e][i] = s.at[e][i] - sm;
        }
        __syncthreads();
        // qmean = pmean + G@innov ; NC = pcov - G@Ccov
        for (int idx = tid; idx < GE * 32; idx += NT) {
            int e = idx >> 5, i = idx & 31;
            float sm = s.pmean[e][i];
            for (int k = 0; k < ADd; k++)
                sm = fmaf(s.Gm[e][i * SG + k], s.innov[e][k], sm);
            s.qmean[e][i] = sm;
        }
        for (int idx = tid; idx < GE * 1024; idx += NT) {
            int e = idx >> 10, r = idx & 1023, i = r >> 5, j = r & 31;
            float sm = s.pcov[e][i * SX + j];
#pragma unroll
            for (int k = 0; k < ADd; k++)
                sm = fmaf(-s.Gm[e][i * SG + k], s.Ccov[e][k * SC + j], sm);
            s.NC[e][i * SX + j] = sm;
        }
        __syncthreads();
        // qcov = 0.5(NC+NC^T) + eps I ; write posterior outputs
        for (int idx = tid; idx < GE * 1024; idx += NT) {
            int e = idx >> 10, r = idx & 1023, i = r >> 5, j = r & 31;
            float v = 0.5f * (s.NC[e][i * SX + j] + s.NC[e][j * SX + i]) +
                      ((i == j) ? EPSV : 0.f);
            s.qcov[e][i * SX + j] = v;
            out[QC_OFF + ((size_t)t * Bd + b0 + e) * 1024 + r] = v;
        }
        for (int idx = tid; idx < GE * 32; idx += NT) {
            int e = idx >> 5, i = idx & 31;
            out[QM_OFF + ((size_t)t * Bd + b0 + e) * 32 + i] = s.qmean[e][i];
        }
        __syncthreads();
    }
}

extern "C" void kernel_launch(void* const* d_in, const int* in_sizes, int n_in,
                              void* d_out, int out_size) {
    const float* u   = (const float*)d_in[0];
    const float* a   = (const float*)d_in[1];
    const float* W1  = (const float*)d_in[2];
    const float* b1  = (const float*)d_in[3];
    const float* W2  = (const float*)d_in[4];
    const float* b2  = (const float*)d_in[5];
    const float* WA  = (const float*)d_in[6];
    const float* bA  = (const float*)d_in[7];
    const float* WB  = (const float*)d_in[8];
    const float* bB  = (const float*)d_in[9];
    const float* WC  = (const float*)d_in[10];
    const float* bC  = (const float*)d_in[11];
    const float* Wnx = (const float*)d_in[12];
    const float* bnx = (const float*)d_in[13];
    const float* Wna = (const float*)d_in[14];
    const float* bna = (const float*)d_in[15];
    const float* alp = (const float*)d_in[16];
    float* out = (float*)d_out;

    cudaFuncSetAttribute(kf_kernel, cudaFuncAttributeMaxDynamicSharedMemorySize,
                         (int)sizeof(Smem));
    kf_kernel<<<Bd / GE, NT, sizeof(Smem)>>>(u, a, W1, b1, W2, b2, WA, bA, WB, bB,
                                             WC, bC, Wnx, bnx, Wna, bna, alp, out);
}

// round 6
// speedup vs baseline: 1.7841x; 1.7841x over previous
#include <cuda_runtime.h>
#include <math.h>

#define Td 128
#define Bd 256
#define Xd 32
#define Ud 8
#define ADd 24
#define Hd 256
#define NT 256
#define GE 2
#define MINV 0.01f
#define MAXV 1.0f
#define EPSV 1e-6f

#define SX 36      // row stride for 32-wide matrices (float4 aligned, banks 4j+k)
#define SCW 36     // row stride for 24x32 matrices
#define SP 25      // row stride for 24x24 S matrices (conflict-free column reads)
#define PPR 1312   // concat prior head outputs: WA(1024)|WB(256)|Wnx(32)
#define PPO 792    // concat post head outputs:  WC(768)|Wna(24)

// --- transposed weight scratch (written by prep kernel each replay) ---
__device__ __align__(16) float g_W1T[32 * 256];
__device__ __align__(16) float g_W2T[256 * 256];
__device__ __align__(16) float g_WprT[256 * PPR];
__device__ __align__(16) float g_WpoT[256 * PPO];
__device__ __align__(16) float g_bpr[PPR];
__device__ __align__(16) float g_bpo[PPO];

struct __align__(16) Smem {
    float qmean[GE][32];
    float pmean[GE][32];
    float nx[GE][32];
    float na[GE][24];
    float innov[GE][24];
    float ut[GE][8];
    float at[GE][24];
    float h1[GE][Hd];
    float h2[GE][Hd];
    float qcov[GE][32 * SX];
    float pcov[GE][32 * SX];
    float Amat[GE][32 * SX];
    float AmatT[GE][32 * SX];
    float T1[GE][32 * SX];
    float NC[GE][32 * SX];
    float Bmt[GE][Xd * Ud];
    float Cm[GE][ADd * SCW];
    float CmT[GE][Xd * ADd];    // CmT[k][l] = Cm[l][k], 32x24
    float Ccov[GE][ADd * SCW];
    float Smat[GE][ADd * SP];
    float Sinv[GE][ADd * SP];
    float Gm[GE][Xd * ADd];     // 32x24, stride 24
};

__device__ __forceinline__ float sigv(float z) {
    return MINV + (MAXV - MINV) / (1.0f + expf(-z));
}

// ---------------- prologue: transpose + concat weights ----------------
__global__ void prep_kernel(const float* __restrict__ W1, const float* __restrict__ W2,
                            const float* __restrict__ WA, const float* __restrict__ bA,
                            const float* __restrict__ WB, const float* __restrict__ bB,
                            const float* __restrict__ Wnx, const float* __restrict__ bnx,
                            const float* __restrict__ WC, const float* __restrict__ bC,
                            const float* __restrict__ Wna, const float* __restrict__ bna) {
    int t0 = blockIdx.x * blockDim.x + threadIdx.x;
    int nth = gridDim.x * blockDim.x;
    for (int i = t0; i < 256 * 32; i += nth) { int p = i >> 5, k = i & 31; g_W1T[k * 256 + p] = W1[i]; }
    for (int i = t0; i < 256 * 256; i += nth) { int p = i >> 8, k = i & 255; g_W2T[k * 256 + p] = W2[i]; }
    for (int i = t0; i < 1024 * 256; i += nth) { int p = i >> 8, k = i & 255; g_WprT[k * PPR + p] = WA[i]; }
    for (int i = t0; i < 256 * 256; i += nth) { int p = i >> 8, k = i & 255; g_WprT[k * PPR + 1024 + p] = WB[i]; }
    for (int i = t0; i < 32 * 256; i += nth) { int p = i >> 8, k = i & 255; g_WprT[k * PPR + 1280 + p] = Wnx[i]; }
    for (int i = t0; i < 768 * 256; i += nth) { int p = i >> 8, k = i & 255; g_WpoT[k * PPO + p] = WC[i]; }
    for (int i = t0; i < 24 * 256; i += nth) { int p = i >> 8, k = i & 255; g_WpoT[k * PPO + 768 + p] = Wna[i]; }
    for (int i = t0; i < 1024; i += nth) g_bpr[i] = bA[i];
    for (int i = t0; i < 256; i += nth) g_bpr[1024 + i] = bB[i];
    for (int i = t0; i < 32; i += nth) g_bpr[1280 + i] = bnx[i];
    for (int i = t0; i < 768; i += nth) g_bpo[i] = bC[i];
    for (int i = t0; i < 24; i += nth) g_bpo[768 + i] = bna[i];
}

// 2-layer MLP: h2 = relu(W2 relu(W1 x + b1) + b2), both elements. NT == Hd == 256.
__device__ __forceinline__ void mlp(Smem& s, const float* __restrict__ x0,
                                    const float* __restrict__ x1,
                                    const float* __restrict__ b1,
                                    const float* __restrict__ b2) {
    const int tid = (int)threadIdx.x;
    {
        float s0 = b1[tid];
        float s1 = s0;
        const float* w = g_W1T + tid;   // coalesced: consecutive threads consecutive floats
#pragma unroll
        for (int k = 0; k < 32; k++) {
            float wv = w[k * 256];
            s0 = fmaf(wv, x0[k], s0);
            s1 = fmaf(wv, x1[k], s1);
        }
        s.h1[0][tid] = fmaxf(s0, 0.f);
        s.h1[1][tid] = fmaxf(s1, 0.f);
    }
    __syncthreads();
    {
        float s0 = b2[tid];
        float s1 = s0;
        const float* w = g_W2T + tid;
#pragma unroll 8
        for (int k = 0; k < 256; k++) {
            float wv = w[k * 256];
            s0 = fmaf(wv, s.h1[0][k], s0);
            s1 = fmaf(wv, s.h1[1][k], s1);
        }
        s.h2[0][tid] = fmaxf(s0, 0.f);
        s.h2[1][tid] = fmaxf(s1, 0.f);
    }
    __syncthreads();
}

__global__ void __launch_bounds__(NT, 1)
kf_kernel(const float* __restrict__ u, const float* __restrict__ a,
          const float* __restrict__ b1, const float* __restrict__ b2,
          const float* __restrict__ alpha_p, float* __restrict__ out) {
    extern __shared__ __align__(16) char smem_raw[];
    Smem& s = *reinterpret_cast<Smem*>(smem_raw);
    const int tid = (int)threadIdx.x;
    const int b0 = (int)blockIdx.x * GE;
    const float alpha = alpha_p[0];

    const size_t PM_OFF = 0;
    const size_t PC_OFF = (size_t)Td * Bd * Xd;
    const size_t QM_OFF = PC_OFF + (size_t)Td * Bd * Xd * Xd;
    const size_t QC_OFF = QM_OFF + (size_t)Td * Bd * Xd;

    for (int t = 0; t < Td; t++) {
        if (t > 0) {
            // ===== PRIOR: dyn(qmean) -> A, B, nx =====
            if (tid < GE * Ud) {
                int e = tid >> 3, j = tid & 7;
                s.ut[e][j] = u[((size_t)(t - 1) * Bd + b0 + e) * Ud + j];
            }
            mlp(s, s.qmean[0], s.qmean[1], b1, b2);
            // heads: coalesced float4 over transposed concat weights
            for (int p4 = tid * 4; p4 < PPR; p4 += NT * 4) {
                const float* w = g_WprT + p4;
                float4 a0 = make_float4(0.f, 0.f, 0.f, 0.f), a1 = a0;
#pragma unroll 4
                for (int k = 0; k < 256; k++) {
                    float4 wv = *(const float4*)(w + k * PPR);
                    float xa = s.h2[0][k], xb = s.h2[1][k];
                    a0.x = fmaf(wv.x, xa, a0.x); a0.y = fmaf(wv.y, xa, a0.y);
                    a0.z = fmaf(wv.z, xa, a0.z); a0.w = fmaf(wv.w, xa, a0.w);
                    a1.x = fmaf(wv.x, xb, a1.x); a1.y = fmaf(wv.y, xb, a1.y);
                    a1.z = fmaf(wv.z, xb, a1.z); a1.w = fmaf(wv.w, xb, a1.w);
                }
                float4 bb = *(const float4*)(g_bpr + p4);
                a0.x += bb.x; a0.y += bb.y; a0.z += bb.z; a0.w += bb.w;
                a1.x += bb.x; a1.y += bb.y; a1.z += bb.z; a1.w += bb.w;
                float v0[4] = {a0.x, a0.y, a0.z, a0.w};
                float v1[4] = {a1.x, a1.y, a1.z, a1.w};
                if (p4 < 1024) {
                    int i = p4 >> 5, j = p4 & 31;
                    float4 am0, am1;
                    float* m0 = (float*)&am0;
                    float* m1 = (float*)&am1;
#pragma unroll
                    for (int d = 0; d < 4; d++) {
                        float dg = (j + d == i) ? 1.f : 0.f;
                        m0[d] = fmaf(alpha, v0[d], dg);
                        m1[d] = fmaf(alpha, v1[d], dg);
                        s.AmatT[0][(j + d) * SX + i] = m0[d];
                        s.AmatT[1][(j + d) * SX + i] = m1[d];
                    }
                    *(float4*)&s.Amat[0][i * SX + j] = am0;
                    *(float4*)&s.Amat[1][i * SX + j] = am1;
                } else if (p4 < 1280) {
                    int q = p4 - 1024;
                    *(float4*)&s.Bmt[0][q] = a0;
                    *(float4*)&s.Bmt[1][q] = a1;
                } else {
                    int q = p4 - 1280;
#pragma unroll
                    for (int d = 0; d < 4; d++) {
                        s.nx[0][q + d] = sigv(v0[d]);
                        s.nx[1][q + d] = sigv(v1[d]);
                    }
                }
            }
            __syncthreads();
            // pmean = A@qmean + B@u
            if (tid < GE * Xd) {
                int e = tid >> 5, i = tid & 31;
                float sm = 0.f;
#pragma unroll 8
                for (int j = 0; j < 32; j++)
                    sm = fmaf(s.Amat[e][i * SX + j], s.qmean[e][j], sm);
#pragma unroll
                for (int j = 0; j < 8; j++)
                    sm = fmaf(s.Bmt[e][i * 8 + j], s.ut[e][j], sm);
                s.pmean[e][i] = sm;
            }
            // T1 = A @ qcov  (float4 over columns)
            for (int idx = tid; idx < GE * 256; idx += NT) {
                int e = idx >> 8, r = idx & 255, i = r >> 3, k4 = (r & 7) << 2;
                float4 acc = make_float4(0.f, 0.f, 0.f, 0.f);
#pragma unroll 8
                for (int j = 0; j < 32; j++) {
                    float av = s.Amat[e][i * SX + j];
                    float4 q = *(const float4*)&s.qcov[e][j * SX + k4];
                    acc.x = fmaf(av, q.x, acc.x); acc.y = fmaf(av, q.y, acc.y);
                    acc.z = fmaf(av, q.z, acc.z); acc.w = fmaf(av, q.w, acc.w);
                }
                *(float4*)&s.T1[e][i * SX + k4] = acc;
            }
            __syncthreads();
            // NC = T1 @ A^T + diag(nx)
            for (int idx = tid; idx < GE * 256; idx += NT) {
                int e = idx >> 8, r = idx & 255, i = r >> 3, j4 = (r & 7) << 2;
                float4 acc = make_float4(0.f, 0.f, 0.f, 0.f);
#pragma unroll 8
                for (int k = 0; k < 32; k++) {
                    float tv = s.T1[e][i * SX + k];
                    float4 av = *(const float4*)&s.AmatT[e][k * SX + j4];
                    acc.x = fmaf(tv, av.x, acc.x); acc.y = fmaf(tv, av.y, acc.y);
                    acc.z = fmaf(tv, av.z, acc.z); acc.w = fmaf(tv, av.w, acc.w);
                }
                float* ac = (float*)&acc;
#pragma unroll
                for (int d = 0; d < 4; d++)
                    if (j4 + d == i) ac[d] += s.nx[e][i];
                *(float4*)&s.NC[e][i * SX + j4] = acc;
            }
            __syncthreads();
            // pcov = 0.5(NC + NC^T) + eps I ; emit prior outputs
            for (int idx = tid; idx < GE * 1024; idx += NT) {
                int e = idx >> 10, r = idx & 1023, i = r >> 5, j = r & 31;
                float v = 0.5f * (s.NC[e][i * SX + j] + s.NC[e][j * SX + i]) +
                          ((i == j) ? EPSV : 0.f);
                s.pcov[e][i * SX + j] = v;
                out[PC_OFF + ((size_t)t * Bd + b0 + e) * 1024 + r] = v;
            }
            if (tid < GE * Xd) {
                int e = tid >> 5, i = tid & 31;
                out[PM_OFF + ((size_t)t * Bd + b0 + e) * 32 + i] = s.pmean[e][i];
            }
            __syncthreads();
        } else {
            if (tid < GE * Xd) {
                int e = tid >> 5, i = tid & 31;
                s.pmean[e][i] = 0.f;
                out[PM_OFF + ((size_t)(b0 + e)) * 32 + i] = 0.f;
            }
            for (int idx = tid; idx < GE * 1024; idx += NT) {
                int e = idx >> 10, r = idx & 1023, i = r >> 5, j = r & 31;
                float v = (i == j) ? 1.f : 0.f;
                s.pcov[e][i * SX + j] = v;
                out[PC_OFF + ((size_t)(b0 + e)) * 1024 + r] = v;
            }
            __syncthreads();
        }

        // ===== POST: dyn(pmean) -> C, na =====
        if (tid < GE * ADd) {
            int e = tid / ADd, j = tid % ADd;
            s.at[e][j] = a[((size_t)t * Bd + b0 + e) * ADd + j];
        }
        mlp(s, s.pmean[0], s.pmean[1], b1, b2);
        for (int p4 = tid * 4; p4 < PPO; p4 += NT * 4) {
            const float* w = g_WpoT + p4;
            float4 a0 = make_float4(0.f, 0.f, 0.f, 0.f), a1 = a0;
#pragma unroll 4
            for (int k = 0; k < 256; k++) {
                float4 wv = *(const float4*)(w + k * PPO);
                float xa = s.h2[0][k], xb = s.h2[1][k];
                a0.x = fmaf(wv.x, xa, a0.x); a0.y = fmaf(wv.y, xa, a0.y);
                a0.z = fmaf(wv.z, xa, a0.z); a0.w = fmaf(wv.w, xa, a0.w);
                a1.x = fmaf(wv.x, xb, a1.x); a1.y = fmaf(wv.y, xb, a1.y);
                a1.z = fmaf(wv.z, xb, a1.z); a1.w = fmaf(wv.w, xb, a1.w);
            }
            float4 bb = *(const float4*)(g_bpo + p4);
            a0.x += bb.x; a0.y += bb.y; a0.z += bb.z; a0.w += bb.w;
            a1.x += bb.x; a1.y += bb.y; a1.z += bb.z; a1.w += bb.w;
            float v0[4] = {a0.x, a0.y, a0.z, a0.w};
            float v1[4] = {a1.x, a1.y, a1.z, a1.w};
            if (p4 < 768) {
                int i = p4 >> 5, j = p4 & 31;
                *(float4*)&s.Cm[0][i * SCW + j] = a0;
                *(float4*)&s.Cm[1][i * SCW + j] = a1;
#pragma unroll
                for (int d = 0; d < 4; d++) {
                    s.CmT[0][(j + d) * ADd + i] = v0[d];
                    s.CmT[1][(j + d) * ADd + i] = v1[d];
                }
            } else {
                int q = p4 - 768;
#pragma unroll
                for (int d = 0; d < 4; d++) {
                    s.na[0][q + d] = sigv(v0[d]);
                    s.na[1][q + d] = sigv(v1[d]);
                }
            }
        }
        __syncthreads();
        // Ccov = C @ pcov
        for (int idx = tid; idx < GE * 192; idx += NT) {
            int e = idx / 192, r = idx % 192, i = r >> 3, k4 = (r & 7) << 2;
            float4 acc = make_float4(0.f, 0.f, 0.f, 0.f);
#pragma unroll 8
            for (int j = 0; j < 32; j++) {
                float cv = s.Cm[e][i * SCW + j];
                float4 p = *(const float4*)&s.pcov[e][j * SX + k4];
                acc.x = fmaf(cv, p.x, acc.x); acc.y = fmaf(cv, p.y, acc.y);
                acc.z = fmaf(cv, p.z, acc.z); acc.w = fmaf(cv, p.w, acc.w);
            }
            *(float4*)&s.Ccov[e][i * SCW + k4] = acc;
        }
        __syncthreads();
        // S = Ccov @ C^T + diag(na) ; innov = a_t - C@pmean
        for (int idx = tid; idx < GE * 144; idx += NT) {
            int e = idx / 144, r = idx % 144, i = r / 6, l4 = (r % 6) << 2;
            float4 acc = make_float4(0.f, 0.f, 0.f, 0.f);
#pragma unroll 8
            for (int k = 0; k < 32; k++) {
                float cv = s.Ccov[e][i * SCW + k];
                float4 cm = *(const float4*)&s.CmT[e][k * ADd + l4];
                acc.x = fmaf(cv, cm.x, acc.x); acc.y = fmaf(cv, cm.y, acc.y);
                acc.z = fmaf(cv, cm.z, acc.z); acc.w = fmaf(cv, cm.w, acc.w);
            }
            float* ac = (float*)&acc;
#pragma unroll
            for (int d = 0; d < 4; d++) {
                float v = ac[d] + ((l4 + d == i) ? s.na[e][i] : 0.f);
                s.Smat[e][i * SP + l4 + d] = v;
            }
        }
        if (tid < GE * ADd) {
            int e = tid / ADd, i = tid % ADd;
            float sm = 0.f;
#pragma unroll 8
            for (int j = 0; j < 32; j++)
                sm = fmaf(s.Cm[e][i * SCW + j], s.pmean[e][j], sm);
            s.innov[e][i] = s.at[e][i] - sm;
        }
        __syncthreads();
        // Warp-local Gauss-Jordan inverse of SPD S (warp e handles element e)
        if (tid < GE * 32) {
            int e = tid >> 5, lane = tid & 31;
            float r[ADd], v[ADd];
            if (lane < ADd) {
#pragma unroll
                for (int c = 0; c < ADd; c++) {
                    r[c] = s.Smat[e][lane * SP + c];
                    v[c] = (c == lane) ? 1.f : 0.f;
                }
            } else {
#pragma unroll
                for (int c = 0; c < ADd; c++) { r[c] = 0.f; v[c] = 0.f; }
            }
#pragma unroll
            for (int j = 0; j < ADd; j++) {
                float pj = __shfl_sync(0xffffffffu, r[j], j);
                float rcp = 1.0f / pj;
                float f = r[j] * rcp;
#pragma unroll
                for (int c = 0; c < ADd; c++) {
                    float rj = __shfl_sync(0xffffffffu, r[c], j);
                    float vj = __shfl_sync(0xffffffffu, v[c], j);
                    if (lane == j) {
                        r[c] = rj * rcp;
                        v[c] = vj * rcp;
                    } else {
                        r[c] = fmaf(-f, rj, r[c]);
                        v[c] = fmaf(-f, vj, v[c]);
                    }
                }
            }
            if (lane < ADd) {
#pragma unroll
                for (int c = 0; c < ADd; c++)
                    s.Sinv[e][lane * SP + c] = v[c];
            }
        }
        __syncthreads();
        // G = Ccov^T @ Sinv   (cov symmetric => cov@C^T = Ccov^T)
        for (int idx = tid; idx < GE * 768; idx += NT) {
            int e = idx / 768, r = idx % 768, i = r / ADd, l = r % ADd;
            float sm = 0.f;
#pragma unroll 8
            for (int k = 0; k < ADd; k++)
                sm = fmaf(s.Ccov[e][k * SCW + i], s.Sinv[e][k * SP + l], sm);
            s.Gm[e][i * ADd + l] = sm;
        }
        __syncthreads();
        // qmean = pmean + G@innov ; NC = pcov - G@Ccov
        if (tid < GE * Xd) {
            int e = tid >> 5, i = tid & 31;
            float sm = s.pmean[e][i];
#pragma unroll 8
            for (int k = 0; k < ADd; k++)
                sm = fmaf(s.Gm[e][i * ADd + k], s.innov[e][k], sm);
            s.qmean[e][i] = sm;
        }
        for (int idx = tid; idx < GE * 256; idx += NT) {
            int e = idx >> 8, r = idx & 255, i = r >> 3, j4 = (r & 7) << 2;
            float4 acc = *(const float4*)&s.pcov[e][i * SX + j4];
#pragma unroll 8
            for (int k = 0; k < ADd; k++) {
                float g = s.Gm[e][i * ADd + k];
                float4 cv = *(const float4*)&s.Ccov[e][k * SCW + j4];
                acc.x = fmaf(-g, cv.x, acc.x); acc.y = fmaf(-g, cv.y, acc.y);
                acc.z = fmaf(-g, cv.z, acc.z); acc.w = fmaf(-g, cv.w, acc.w);
            }
            *(float4*)&s.NC[e][i * SX + j4] = acc;
        }
        __syncthreads();
        // qcov = 0.5(NC + NC^T) + eps I ; emit posterior outputs
        for (int idx = tid; idx < GE * 1024; idx += NT) {
            int e = idx >> 10, r = idx & 1023, i = r >> 5, j = r & 31;
            float v = 0.5f * (s.NC[e][i * SX + j] + s.NC[e][j * SX + i]) +
                      ((i == j) ? EPSV : 0.f);
            s.qcov[e][i * SX + j] = v;
            out[QC_OFF + ((size_t)t * Bd + b0 + e) * 1024 + r] = v;
        }
        if (tid < GE * Xd) {
            int e = tid >> 5, i = tid & 31;
            out[QM_OFF + ((size_t)t * Bd + b0 + e) * 32 + i] = s.qmean[e][i];
        }
        __syncthreads();
    }
}

extern "C" void kernel_launch(void* const* d_in, const int* in_sizes, int n_in,
                              void* d_out, int out_size) {
    const float* u   = (const float*)d_in[0];
    const float* a   = (const float*)d_in[1];
    const float* W1  = (const float*)d_in[2];
    const float* b1  = (const float*)d_in[3];
    const float* W2  = (const float*)d_in[4];
    const float* b2  = (const float*)d_in[5];
    const float* WA  = (const float*)d_in[6];
    const float* bA  = (const float*)d_in[7];
    const float* WB  = (const float*)d_in[8];
    const float* bB  = (const float*)d_in[9];
    const float* WC  = (const float*)d_in[10];
    const float* bC  = (const float*)d_in[11];
    const float* Wnx = (const float*)d_in[12];
    const float* bnx = (const float*)d_in[13];
    const float* Wna = (const float*)d_in[14];
    const float* bna = (const float*)d_in[15];
    const float* alp = (const float*)d_in[16];
    float* out = (float*)d_out;

    prep_kernel<<<128, 256>>>(W1, W2, WA, bA, WB, bB, Wnx, bnx, WC, bC, Wna, bna);

    cudaFuncSetAttribute(kf_kernel, cudaFuncAttributeMaxDynamicSharedMemorySize,
                         (int)sizeof(Smem));
    kf_kernel<<<Bd / GE, NT, sizeof(Smem)>>>(u, a, b1, b2, alp, out);
}

// round 10
// speedup vs baseline: 2.0201x; 1.1323x over previous
#include <cuda_runtime.h>
#include <math.h>

#define Td 128
#define Bd 256
#define Xd 32
#define Ud 8
#define ADd 24
#define Hd 256
#define NT 512
#define GE 2
#define MINV 0.01f
#define MAXV 1.0f
#define EPSV 1e-6f

#define SX2 34     // float2 row stride for 32-wide matrices (even -> 16B-aligned pairs)
#define SC2 34     // float2 row stride for 24x32 matrices
#define SP  25     // scalar row stride for per-element 24x24 GJ matrices
#define PPR 1312   // concat prior head outputs: WA(1024)|WB(256)|Wnx(32)
#define PPO 792    // concat post head outputs:  WC(768)|Wna(24)

// --- transposed + lane-duplicated weights (written by prep kernel each replay) ---
__device__ __align__(16) float2 g_W1T2[32 * 256];
__device__ __align__(16) float2 g_W2T2[256 * 256];
__device__ __align__(16) float2 g_WprT2[256 * PPR];
__device__ __align__(16) float2 g_WpoT2[256 * PPO];
__device__ __align__(16) float2 g_bpr2[PPR];
__device__ __align__(16) float2 g_bpo2[PPO];

struct __align__(16) Smem {
    float2 qmean[32], pmean[32], nx[32], na[24], innovN[24], ut[8], at[24];
    float2 h1[256], h2[256], psum[256];
    float2 qcov[32 * SX2], pcov[32 * SX2];
    float2 Amat[32 * SX2], AmatT[32 * SX2], T1[32 * SX2], NC[32 * SX2];
    float2 Bmt[32 * 8];
    float2 Cm[24 * SC2], Ccov[24 * SC2];
    float2 CmT[32 * 24];
    float2 Sinv2[24 * 24];
    float2 Gm[32 * 24];          // Gn = -(Ccov^T @ Sinv), stride 24
    float  Smat[GE][24 * SP];    // scalar per element for warp-local GJ
};

// packed fp32x2 FMA (FFMA2) — IEEE fma per lane, 2x FFMA throughput
__device__ __forceinline__ float2 ffma2(float2 a, float2 b, float2 c) {
    union U { float2 f; unsigned long long u; };
    U A, B, C, D;
    A.f = a; B.f = b; C.f = c;
    asm("fma.rn.f32x2 %0, %1, %2, %3;" : "=l"(D.u) : "l"(A.u), "l"(B.u), "l"(C.u));
    return D.f;
}

__device__ __forceinline__ float sigv(float z) {
    return MINV + (MAXV - MINV) / (1.0f + expf(-z));
}

// ---------------- prologue: transpose + concat + lane-duplicate weights ----------------
__global__ void prep_kernel(const float* __restrict__ W1, const float* __restrict__ W2,
                            const float* __restrict__ WA, const float* __restrict__ bA,
                            const float* __restrict__ WB, const float* __restrict__ bB,
                            const float* __restrict__ Wnx, const float* __restrict__ bnx,
                            const float* __restrict__ WC, const float* __restrict__ bC,
                            const float* __restrict__ Wna, const float* __restrict__ bna) {
    int t0 = blockIdx.x * blockDim.x + threadIdx.x;
    int nth = gridDim.x * blockDim.x;
    for (int i = t0; i < 256 * 32; i += nth) { int p = i >> 5, k = i & 31; float v = W1[i]; g_W1T2[k * 256 + p] = make_float2(v, v); }
    for (int i = t0; i < 256 * 256; i += nth) { int p = i >> 8, k = i & 255; float v = W2[i]; g_W2T2[k * 256 + p] = make_float2(v, v); }
    for (int i = t0; i < 1024 * 256; i += nth) { int p = i >> 8, k = i & 255; float v = WA[i]; g_WprT2[k * PPR + p] = make_float2(v, v); }
    for (int i = t0; i < 256 * 256; i += nth) { int p = i >> 8, k = i & 255; float v = WB[i]; g_WprT2[k * PPR + 1024 + p] = make_float2(v, v); }
    for (int i = t0; i < 32 * 256; i += nth) { int p = i >> 8, k = i & 255; float v = Wnx[i]; g_WprT2[k * PPR + 1280 + p] = make_float2(v, v); }
    for (int i = t0; i < 768 * 256; i += nth) { int p = i >> 8, k = i & 255; float v = WC[i]; g_WpoT2[k * PPO + p] = make_float2(v, v); }
    for (int i = t0; i < 24 * 256; i += nth) { int p = i >> 8, k = i & 255; float v = Wna[i]; g_WpoT2[k * PPO + 768 + p] = make_float2(v, v); }
    for (int i = t0; i < 1024; i += nth) { float v = bA[i]; g_bpr2[i] = make_float2(v, v); }
    for (int i = t0; i < 256; i += nth) { float v = bB[i]; g_bpr2[1024 + i] = make_float2(v, v); }
    for (int i = t0; i < 32; i += nth) { float v = bnx[i]; g_bpr2[1280 + i] = make_float2(v, v); }
    for (int i = t0; i < 768; i += nth) { float v = bC[i]; g_bpo2[i] = make_float2(v, v); }
    for (int i = t0; i < 24; i += nth) { float v = bna[i]; g_bpo2[768 + i] = make_float2(v, v); }
}

// 2-layer MLP, packed 2 elements, 2-way split-K across 512 threads.
__device__ __forceinline__ void mlp2(Smem& s, const float2* __restrict__ x,
                                     const float* __restrict__ b1,
                                     const float* __restrict__ b2) {
    const int tid = (int)threadIdx.x;
    const int p = tid & 255, kh = tid >> 8;
    // layer 1 (K=32)
    {
        float2 acc;
        if (kh == 0) { float bb = b1[p]; acc = make_float2(bb, bb); }
        else acc = make_float2(0.f, 0.f);
        const float2* w = g_W1T2 + p;
        int k0 = kh * 16;
#pragma unroll
        for (int k = 0; k < 16; k++)
            acc = ffma2(w[(k0 + k) * 256], x[k0 + k], acc);
        if (kh) s.psum[p] = acc;
        __syncthreads();
        if (!kh) {
            float2 o = s.psum[p];
            s.h1[p] = make_float2(fmaxf(acc.x + o.x, 0.f), fmaxf(acc.y + o.y, 0.f));
        }
        __syncthreads();
    }
    // layer 2 (K=256)
    {
        float2 acc0, acc1;
        if (kh == 0) { float bb = b2[p]; acc0 = make_float2(bb, bb); }
        else acc0 = make_float2(0.f, 0.f);
        acc1 = make_float2(0.f, 0.f);
        const float2* w = g_W2T2 + p;
        int k0 = kh * 128;
#pragma unroll 8
        for (int k = 0; k < 128; k += 2) {
            acc0 = ffma2(w[(k0 + k) * 256], s.h1[k0 + k], acc0);
            acc1 = ffma2(w[(k0 + k + 1) * 256], s.h1[k0 + k + 1], acc1);
        }
        acc0.x += acc1.x; acc0.y += acc1.y;
        if (kh) s.psum[p] = acc0;
        __syncthreads();
        if (!kh) {
            float2 o = s.psum[p];
            s.h2[p] = make_float2(fmaxf(acc0.x + o.x, 0.f), fmaxf(acc0.y + o.y, 0.f));
        }
        __syncthreads();
    }
}

__global__ void __launch_bounds__(NT, 1)
kf_kernel(const float* __restrict__ u, const float* __restrict__ a,
          const float* __restrict__ b1, const float* __restrict__ b2,
          const float* __restrict__ alpha_p, float* __restrict__ out) {
    extern __shared__ __align__(16) char smem_raw[];
    Smem& s = *reinterpret_cast<Smem*>(smem_raw);
    const int tid = (int)threadIdx.x;
    const int b0 = (int)blockIdx.x * GE;
    const float alpha = alpha_p[0];
    const float2 alpha2 = make_float2(alpha, alpha);

    const size_t PM_OFF = 0;
    const size_t PC_OFF = (size_t)Td * Bd * Xd;
    const size_t QM_OFF = PC_OFF + (size_t)Td * Bd * Xd * Xd;
    const size_t QC_OFF = QM_OFF + (size_t)Td * Bd * Xd;

    for (int t = 0; t < Td; t++) {
        if (t > 0) {
            // ===== PRIOR: dyn(qmean) -> A, B, nx =====
            if (tid < Ud) {
                size_t base = ((size_t)(t - 1) * Bd + b0) * Ud + tid;
                s.ut[tid] = make_float2(u[base], u[base + Ud]);
            }
            mlp2(s, s.qmean, b1, b2);
            // prior heads: 328 active threads, 1 round, dup-weights, FFMA2
            {
                int p4 = tid * 4;
                if (p4 < PPR) {
                    const float2* w = g_WprT2 + p4;
                    float2 ac0 = make_float2(0.f, 0.f), ac1 = ac0, ac2 = ac0, ac3 = ac0;
#pragma unroll 4
                    for (int k = 0; k < 256; k++) {
                        const float4* w4 = (const float4*)(w + (size_t)k * PPR);
                        float4 wa = w4[0], wb = w4[1];
                        float2 hk = s.h2[k];
                        ac0 = ffma2(make_float2(wa.x, wa.y), hk, ac0);
                        ac1 = ffma2(make_float2(wa.z, wa.w), hk, ac1);
                        ac2 = ffma2(make_float2(wb.x, wb.y), hk, ac2);
                        ac3 = ffma2(make_float2(wb.z, wb.w), hk, ac3);
                    }
                    float2 vv[4] = {ac0, ac1, ac2, ac3};
#pragma unroll
                    for (int d = 0; d < 4; d++) {
                        float2 bb = g_bpr2[p4 + d];
                        float2 v2 = make_float2(vv[d].x + bb.x, vv[d].y + bb.y);
                        if (p4 < 1024) {
                            int i = p4 >> 5, jd = (p4 & 31) + d;
                            float dg = (jd == i) ? 1.f : 0.f;
                            float2 am = ffma2(alpha2, v2, make_float2(dg, dg));
                            s.Amat[i * SX2 + jd] = am;
                            s.AmatT[jd * SX2 + i] = am;
                        } else if (p4 < 1280) {
                            s.Bmt[p4 - 1024 + d] = v2;
                        } else {
                            s.nx[p4 - 1280 + d] = make_float2(sigv(v2.x), sigv(v2.y));
                        }
                    }
                }
            }
            __syncthreads();
            // pmean = A@qmean + B@u ; T1 = A@qcov
            if (tid < 32) {
                int i = tid;
                float2 acc = make_float2(0.f, 0.f);
#pragma unroll 8
                for (int j = 0; j < 32; j++)
                    acc = ffma2(s.Amat[i * SX2 + j], s.qmean[j], acc);
#pragma unroll
                for (int j = 0; j < 8; j++)
                    acc = ffma2(s.Bmt[i * 8 + j], s.ut[j], acc);
                s.pmean[i] = acc;
            }
            {
                int i = tid >> 4, k2 = (tid & 15) << 1;
                float2 acc0 = make_float2(0.f, 0.f), acc1 = acc0;
#pragma unroll 8
                for (int j = 0; j < 32; j++) {
                    float2 av = s.Amat[i * SX2 + j];
                    float4 qv = *(const float4*)&s.qcov[j * SX2 + k2];
                    acc0 = ffma2(av, make_float2(qv.x, qv.y), acc0);
                    acc1 = ffma2(av, make_float2(qv.z, qv.w), acc1);
                }
                *(float4*)&s.T1[i * SX2 + k2] = make_float4(acc0.x, acc0.y, acc1.x, acc1.y);
            }
            __syncthreads();
            // NC = T1 @ A^T + diag(nx)
            {
                int i = tid >> 4, j2 = (tid & 15) << 1;
                float2 acc0 = make_float2(0.f, 0.f), acc1 = acc0;
#pragma unroll 8
                for (int k = 0; k < 32; k++) {
                    float2 tv = s.T1[i * SX2 + k];
                    float4 av = *(const float4*)&s.AmatT[k * SX2 + j2];
                    acc0 = ffma2(tv, make_float2(av.x, av.y), acc0);
                    acc1 = ffma2(tv, make_float2(av.z, av.w), acc1);
                }
                if (j2 == i) { float2 n = s.nx[i]; acc0.x += n.x; acc0.y += n.y; }
                if (j2 + 1 == i) { float2 n = s.nx[i]; acc1.x += n.x; acc1.y += n.y; }
                *(float4*)&s.NC[i * SX2 + j2] = make_float4(acc0.x, acc0.y, acc1.x, acc1.y);
            }
            __syncthreads();
            // pcov = 0.5(NC + NC^T) + eps I ; emit prior outputs
            for (int idx = tid; idx < 1024; idx += NT) {
                int i = idx >> 5, j = idx & 31;
                float2 nij = s.NC[i * SX2 + j], nji = s.NC[j * SX2 + i];
                float d = (i == j) ? EPSV : 0.f;
                float2 v = make_float2(0.5f * (nij.x + nji.x) + d, 0.5f * (nij.y + nji.y) + d);
                s.pcov[i * SX2 + j] = v;
                out[PC_OFF + ((size_t)t * Bd + b0) * 1024 + idx] = v.x;
                out[PC_OFF + ((size_t)t * Bd + b0 + 1) * 1024 + idx] = v.y;
            }
            if (tid < 32) {
                float2 v = s.pmean[tid];
                out[PM_OFF + ((size_t)t * Bd + b0) * 32 + tid] = v.x;
                out[PM_OFF + ((size_t)t * Bd + b0 + 1) * 32 + tid] = v.y;
            }
            __syncthreads();
        } else {
            if (tid < 32) {
                s.pmean[tid] = make_float2(0.f, 0.f);
                out[PM_OFF + (size_t)b0 * 32 + tid] = 0.f;
                out[PM_OFF + (size_t)(b0 + 1) * 32 + tid] = 0.f;
            }
            for (int idx = tid; idx < 1024; idx += NT) {
                int i = idx >> 5, j = idx & 31;
                float v = (i == j) ? 1.f : 0.f;
                s.pcov[i * SX2 + j] = make_float2(v, v);
                out[PC_OFF + (size_t)b0 * 1024 + idx] = v;
                out[PC_OFF + (size_t)(b0 + 1) * 1024 + idx] = v;
            }
            __syncthreads();
        }

        // ===== POST: dyn(pmean) -> C, na =====
        if (tid < ADd) {
            size_t base = ((size_t)t * Bd + b0) * ADd + tid;
            s.at[tid] = make_float2(a[base], a[base + ADd]);
        }
        mlp2(s, s.pmean, b1, b2);
        // post heads: 198 active threads
        {
            int p4 = tid * 4;
            if (p4 < PPO) {
                const float2* w = g_WpoT2 + p4;
                float2 ac0 = make_float2(0.f, 0.f), ac1 = ac0, ac2 = ac0, ac3 = ac0;
#pragma unroll 4
                for (int k = 0; k < 256; k++) {
                    const float4* w4 = (const float4*)(w + (size_t)k * PPO);
                    float4 wa = w4[0], wb = w4[1];
                    float2 hk = s.h2[k];
                    ac0 = ffma2(make_float2(wa.x, wa.y), hk, ac0);
                    ac1 = ffma2(make_float2(wa.z, wa.w), hk, ac1);
                    ac2 = ffma2(make_float2(wb.x, wb.y), hk, ac2);
                    ac3 = ffma2(make_float2(wb.z, wb.w), hk, ac3);
                }
                float2 vv[4] = {ac0, ac1, ac2, ac3};
#pragma unroll
                for (int d = 0; d < 4; d++) {
                    float2 bb = g_bpo2[p4 + d];
                    float2 v2 = make_float2(vv[d].x + bb.x, vv[d].y + bb.y);
                    if (p4 < 768) {
                        int i = p4 >> 5, jd = (p4 & 31) + d;
                        s.Cm[i * SC2 + jd] = v2;
                        s.CmT[jd * 24 + i] = v2;
                    } else {
                        s.na[p4 - 768 + d] = make_float2(sigv(v2.x), sigv(v2.y));
                    }
                }
            }
        }
        __syncthreads();
        // Ccov = C @ pcov ; innovN = C@pmean - a_t
        if (tid < 384) {
            int i = tid >> 4, k2 = (tid & 15) << 1;
            float2 acc0 = make_float2(0.f, 0.f), acc1 = acc0;
#pragma unroll 8
            for (int j = 0; j < 32; j++) {
                float2 cv = s.Cm[i * SC2 + j];
                float4 pv = *(const float4*)&s.pcov[j * SX2 + k2];
                acc0 = ffma2(cv, make_float2(pv.x, pv.y), acc0);
                acc1 = ffma2(cv, make_float2(pv.z, pv.w), acc1);
            }
            *(float4*)&s.Ccov[i * SC2 + k2] = make_float4(acc0.x, acc0.y, acc1.x, acc1.y);
        } else if (tid < 384 + ADd) {
            int i = tid - 384;
            float2 acc = make_float2(0.f, 0.f);
#pragma unroll 8
            for (int j = 0; j < 32; j++)
                acc = ffma2(s.Cm[i * SC2 + j], s.pmean[j], acc);
            float2 av = s.at[i];
            s.innovN[i] = make_float2(acc.x - av.x, acc.y - av.y);
        }
        __syncthreads();
        // S = Ccov @ C^T + diag(na) -> unpack to per-element scalar Smat
        for (int idx = tid; idx < ADd * ADd; idx += NT) {
            int i = idx / ADd, l = idx % ADd;
            float2 acc = make_float2(0.f, 0.f);
#pragma unroll 8
            for (int k = 0; k < 32; k++)
                acc = ffma2(s.Ccov[i * SC2 + k], s.CmT[k * 24 + l], acc);
            if (i == l) { float2 n = s.na[i]; acc.x += n.x; acc.y += n.y; }
            s.Smat[0][i * SP + l] = acc.x;
            s.Smat[1][i * SP + l] = acc.y;
        }
        __syncthreads();
        // Warp-local Gauss-Jordan inverse of SPD S (2 warps, one per element)
        if (tid < GE * 32) {
            int e = tid >> 5, lane = tid & 31;
            float r[ADd], v[ADd];
            if (lane < ADd) {
#pragma unroll
                for (int c = 0; c < ADd; c++) {
                    r[c] = s.Smat[e][lane * SP + c];
                    v[c] = (c == lane) ? 1.f : 0.f;
                }
            } else {
#pragma unroll
                for (int c = 0; c < ADd; c++) { r[c] = 0.f; v[c] = 0.f; }
            }
#pragma unroll
            for (int j = 0; j < ADd; j++) {
                float pj = __shfl_sync(0xffffffffu, r[j], j);
                float rcp = 1.0f / pj;
                float f = r[j] * rcp;
#pragma unroll
                for (int c = 0; c < ADd; c++) {
                    float rj = __shfl_sync(0xffffffffu, r[c], j);
                    float vj = __shfl_sync(0xffffffffu, v[c], j);
                    if (lane == j) { r[c] = rj * rcp; v[c] = vj * rcp; }
                    else { r[c] = fmaf(-f, rj, r[c]); v[c] = fmaf(-f, vj, v[c]); }
                }
            }
            if (lane < ADd) {
#pragma unroll
                for (int c = 0; c < ADd; c++)
                    ((float*)&s.Sinv2[lane * 24 + c])[e] = v[c];
            }
        }
        __syncthreads();
        // Gn = -(Ccov^T @ Sinv)
        for (int idx = tid; idx < 32 * ADd; idx += NT) {
            int i = idx / ADd, l = idx % ADd;
            float2 acc = make_float2(0.f, 0.f);
#pragma unroll 8
            for (int k = 0; k < ADd; k++)
                acc = ffma2(s.Ccov[k * SC2 + i], s.Sinv2[k * 24 + l], acc);
            s.Gm[i * 24 + l] = make_float2(-acc.x, -acc.y);
        }
        __syncthreads();
        // qmean = pmean + Gn@innovN ; NC = pcov + Gn@Ccov
        if (tid < 32) {
            int i = tid;
            float2 acc = s.pmean[i];
#pragma unroll 8
            for (int k = 0; k < ADd; k++)
                acc = ffma2(s.Gm[i * 24 + k], s.innovN[k], acc);
            s.qmean[i] = acc;
        }
        {
            int i = tid >> 4, j2 = (tid & 15) << 1;
            float4 pv = *(const float4*)&s.pcov[i * SX2 + j2];
            float2 acc0 = make_float2(pv.x, pv.y), acc1 = make_float2(pv.z, pv.w);
#pragma unroll 8
            for (int k = 0; k < ADd; k++) {
                float2 g = s.Gm[i * 24 + k];
                float4 cv = *(const float4*)&s.Ccov[k * SC2 + j2];
                acc0 = ffma2(g, make_float2(cv.x, cv.y), acc0);
                acc1 = ffma2(g, make_float2(cv.z, cv.w), acc1);
            }
            *(float4*)&s.NC[i * SX2 + j2] = make_float4(acc0.x, acc0.y, acc1.x, acc1.y);
        }
        __syncthreads();
        // qcov = 0.5(NC + NC^T) + eps I ; emit posterior outputs
        for (int idx = tid; idx < 1024; idx += NT) {
            int i = idx >> 5, j = idx & 31;
            float2 nij = s.NC[i * SX2 + j], nji = s.NC[j * SX2 + i];
            float d = (i == j) ? EPSV : 0.f;
            float2 v = make_float2(0.5f * (nij.x + nji.x) + d, 0.5f * (nij.y + nji.y) + d);
            s.qcov[i * SX2 + j] = v;
            out[QC_OFF + ((size_t)t * Bd + b0) * 1024 + idx] = v.x;
            out[QC_OFF + ((size_t)t * Bd + b0 + 1) * 1024 + idx] = v.y;
        }
        if (tid < 32) {
            float2 v = s.qmean[tid];
            out[QM_OFF + ((size_t)t * Bd + b0) * 32 + tid] = v.x;
            out[QM_OFF + ((size_t)t * Bd + b0 + 1) * 32 + tid] = v.y;
        }
        __syncthreads();
    }
}

extern "C" void kernel_launch(void* const* d_in, const int* in_sizes, int n_in,
                              void* d_out, int out_size) {
    const float* u   = (const float*)d_in[0];
    const float* a   = (const float*)d_in[1];
    const float* W1  = (const float*)d_in[2];
    const float* b1  = (const float*)d_in[3];
    const float* W2  = (const float*)d_in[4];
    const float* b2  = (const float*)d_in[5];
    const float* WA  = (const float*)d_in[6];
    const float* bA  = (const float*)d_in[7];
    const float* WB  = (const float*)d_in[8];
    const float* bB  = (const float*)d_in[9];
    const float* WC  = (const float*)d_in[10];
    const float* bC  = (const float*)d_in[11];
    const float* Wnx = (const float*)d_in[12];
    const float* bnx = (const float*)d_in[13];
    const float* Wna = (const float*)d_in[14];
    const float* bna = (const float*)d_in[15];
    const float* alp = (const float*)d_in[16];
    float* out = (float*)d_out;

    prep_kernel<<<128, 256>>>(W1, W2, WA, bA, WB, bB, Wnx, bnx, WC, bC, Wna, bna);

    cudaFuncSetAttribute(kf_kernel, cudaFuncAttributeMaxDynamicSharedMemorySize,
                         (int)sizeof(Smem));
    kf_kernel<<<Bd / GE, NT, sizeof(Smem)>>>(u, a, b1, b2, alp, out);
}